// round 2
// baseline (speedup 1.0000x reference)
#include <cuda_runtime.h>
#include <cuda_bf16.h>

typedef unsigned int u32;

#define B_   128
#define T_   64
#define G_   8
#define HID  512
#define H3   1536
#define IN_  1028
#define KA   1056
#define MTOK (B_*T_)

__device__ __align__(16) __nv_bfloat16 g_xhi[MTOK*KA];
__device__ __align__(16) __nv_bfloat16 g_xlo[MTOK*KA];
__device__ __align__(16) __nv_bfloat16 g_wih_hi[G_*H3*KA];
__device__ __align__(16) __nv_bfloat16 g_wih_lo[G_*H3*KA];
__device__ __align__(16) __nv_bfloat16 g_whh_hi[G_*H3*HID];
__device__ __align__(16) __nv_bfloat16 g_whh_lo[G_*H3*HID];
__device__ float g_xp[(size_t)G_*T_*B_*H3];
__device__ float g_h[2][G_*B_*HID];
__device__ __align__(16) __nv_bfloat16 g_hhi[2][G_*B_*HID];
__device__ __align__(16) __nv_bfloat16 g_hlo[2][G_*B_*HID];

__device__ __forceinline__ void bsplit(float v, __nv_bfloat16& hi, __nv_bfloat16& lo) {
    hi = __float2bfloat16(v);
    lo = __float2bfloat16(v - __bfloat162float(hi));
}
__device__ __forceinline__ void ldsm4(u32* r, const void* p) {
    u32 a = (u32)__cvta_generic_to_shared(p);
    asm volatile("ldmatrix.sync.aligned.m8n8.x4.shared.b16 {%0,%1,%2,%3}, [%4];"
                 : "=r"(r[0]), "=r"(r[1]), "=r"(r[2]), "=r"(r[3]) : "r"(a));
}
__device__ __forceinline__ void mma16816(float* d, const u32* a, u32 b0, u32 b1) {
    asm volatile("mma.sync.aligned.m16n8k16.row.col.f32.bf16.bf16.f32 "
                 "{%0,%1,%2,%3}, {%4,%5,%6,%7}, {%8,%9}, {%0,%1,%2,%3};"
                 : "+f"(d[0]), "+f"(d[1]), "+f"(d[2]), "+f"(d[3])
                 : "r"(a[0]), "r"(a[1]), "r"(a[2]), "r"(a[3]), "r"(b0), "r"(b1));
}

__global__ void pack_x_kernel(const float* __restrict__ z, const float* __restrict__ a) {
    int idx = blockIdx.x * blockDim.x + threadIdx.x;
    if (idx >= MTOK * KA) return;
    int m = idx / KA, k = idx - m * KA;
    int b = m >> 6, t = m & 63;
    float v = 0.f;
    if (k < 4)        v = a[(size_t)(b * T_ + t) * 4 + k];
    else if (k < IN_) v = z[(size_t)(b * T_ + t) * 1024 + (k - 4)];
    __nv_bfloat16 hi, lo; bsplit(v, hi, lo);
    g_xhi[idx] = hi; g_xlo[idx] = lo;
}
__global__ void conv_wih_kernel(const float* __restrict__ W) {
    int idx = blockIdx.x * blockDim.x + threadIdx.x;
    if (idx >= G_ * H3 * KA) return;
    int row = idx / KA, k = idx - row * KA;
    float v = (k < IN_) ? W[(size_t)row * IN_ + k] : 0.f;
    __nv_bfloat16 hi, lo; bsplit(v, hi, lo);
    g_wih_hi[idx] = hi; g_wih_lo[idx] = lo;
}
__global__ void conv_whh_kernel(const float* __restrict__ W) {
    int idx = blockIdx.x * blockDim.x + threadIdx.x;
    if (idx >= G_ * H3 * HID) return;
    __nv_bfloat16 hi, lo; bsplit(W[idx], hi, lo);
    g_whh_hi[idx] = hi; g_whh_lo[idx] = lo;
}
__global__ void init_h_kernel(const float* __restrict__ hin) {
    int idx = blockIdx.x * blockDim.x + threadIdx.x;
    if (idx >= G_ * B_ * HID) return;
    int g = idx / (B_ * HID), r = idx - g * B_ * HID;
    int b = r / HID, c = r - b * HID;
    float v = hin[(size_t)b * (G_ * HID) + g * HID + c];
    g_h[0][idx] = v;
    __nv_bfloat16 hi, lo; bsplit(v, hi, lo);
    g_hhi[0][idx] = hi; g_hlo[0][idx] = lo;
}

// C[m, g*1536+j] = x @ W_ih[g]^T + b_ih. grid (96,64), 256 thr, tile 128x128, BK=32.
__global__ void __launch_bounds__(256) gemmA_kernel(const float* __restrict__ b_ih) {
    const int nt = blockIdx.x, mt = blockIdx.y;
    const int g = nt / 12, jb = (nt % 12) * 128, m0 = mt * 128;
    __shared__ __align__(16) __nv_bfloat16 sAhi[128][40];
    __shared__ __align__(16) __nv_bfloat16 sAlo[128][40];
    __shared__ __align__(16) u32 sB[128][36];
    const int tid = threadIdx.x, lane = tid & 31, warp = tid >> 5;
    const int wm = warp >> 1, wn = warp & 1;
    float d[2][8][4];
    #pragma unroll
    for (int i = 0; i < 2; i++) for (int j = 0; j < 8; j++) for (int k = 0; k < 4; k++) d[i][j][k] = 0.f;
    const int r0 = tid >> 2, kc = (tid & 3) * 8;
    uint4 pAh[2], pAl[2], pBh[2], pBl[2];
    #pragma unroll
    for (int i = 0; i < 2; i++) {
        int r = r0 + i * 64;
        size_t ao = (size_t)(m0 + r) * KA + kc;
        pAh[i] = *(const uint4*)(g_xhi + ao); pAl[i] = *(const uint4*)(g_xlo + ao);
        size_t bo = (size_t)(g * H3 + jb + r) * KA + kc;
        pBh[i] = *(const uint4*)(g_wih_hi + bo); pBl[i] = *(const uint4*)(g_wih_lo + bo);
    }
    #pragma unroll
    for (int i = 0; i < 2; i++) {
        int r = r0 + i * 64;
        *(uint4*)&sAhi[r][kc] = pAh[i]; *(uint4*)&sAlo[r][kc] = pAl[i];
        uint4 h = pBh[i], l = pBl[i], w0, w1;
        w0.x = h.x; w0.y = l.x; w0.z = h.y; w0.w = l.y;
        w1.x = h.z; w1.y = l.z; w1.z = h.w; w1.w = l.w;
        *(uint4*)&sB[r][kc] = w0; *(uint4*)&sB[r][kc + 4] = w1;
    }
    __syncthreads();
    const int NIT = KA / 32;
    for (int it = 0; it < NIT; ++it) {
        if (it + 1 < NIT) {
            const int kk = (it + 1) * 32;
            #pragma unroll
            for (int i = 0; i < 2; i++) {
                int r = r0 + i * 64;
                size_t ao = (size_t)(m0 + r) * KA + kk + kc;
                pAh[i] = *(const uint4*)(g_xhi + ao); pAl[i] = *(const uint4*)(g_xlo + ao);
                size_t bo = (size_t)(g * H3 + jb + r) * KA + kk + kc;
                pBh[i] = *(const uint4*)(g_wih_hi + bo); pBl[i] = *(const uint4*)(g_wih_lo + bo);
            }
        }
        #pragma unroll
        for (int ks = 0; ks < 2; ks++) {
            u32 ah[2][4], al[2][4];
            #pragma unroll
            for (int mf = 0; mf < 2; mf++) {
                const int row = wm * 32 + mf * 16 + (lane & 15);
                const int col = ks * 16 + ((lane >> 4) << 3);
                ldsm4(ah[mf], &sAhi[row][col]); ldsm4(al[mf], &sAlo[row][col]);
            }
            #pragma unroll
            for (int nf = 0; nf < 8; nf++) {
                const int n = wn * 64 + nf * 8 + (lane >> 2);
                const int w0 = ks * 16 + ((lane & 3) << 1);
                uint2 q0 = *(const uint2*)&sB[n][w0];
                uint2 q1 = *(const uint2*)&sB[n][w0 + 8];
                #pragma unroll
                for (int mf = 0; mf < 2; mf++) {
                    mma16816(d[mf][nf], ah[mf], q0.x, q1.x);
                    mma16816(d[mf][nf], al[mf], q0.x, q1.x);
                    mma16816(d[mf][nf], ah[mf], q0.y, q1.y);
                }
            }
        }
        if (it + 1 < NIT) {
            __syncthreads();
            #pragma unroll
            for (int i = 0; i < 2; i++) {
                int r = r0 + i * 64;
                *(uint4*)&sAhi[r][kc] = pAh[i]; *(uint4*)&sAlo[r][kc] = pAl[i];
                uint4 h = pBh[i], l = pBl[i], w0, w1;
                w0.x = h.x; w0.y = l.x; w0.z = h.y; w0.w = l.y;
                w1.x = h.z; w1.y = l.z; w1.z = h.w; w1.w = l.w;
                *(uint4*)&sB[r][kc] = w0; *(uint4*)&sB[r][kc + 4] = w1;
            }
            __syncthreads();
        }
    }
    #pragma unroll
    for (int mf = 0; mf < 2; mf++)
        #pragma unroll
        for (int nf = 0; nf < 8; nf++)
            #pragma unroll
            for (int e = 0; e < 4; e++) {
                int row = wm * 32 + mf * 16 + (lane >> 2) + ((e >> 1) << 3);
                int j = jb + wn * 64 + nf * 8 + ((lane & 3) << 1) + (e & 1);
                int m = m0 + row, b = m >> 6, t = m & 63;
                g_xp[(size_t)((g * T_ + t) * B_ + b) * H3 + j] = d[mf][nf][e] + b_ih[g * H3 + j];
            }
}

// one launch per t. grid (8,8,2): g, col-tile(64), batch-tile(64). 256 thr.
__global__ void __launch_bounds__(256) gru_step_kernel(const float* __restrict__ b_hh,
                                                       float* __restrict__ out,
                                                       int t, int rb, int wb) {
    const int g = blockIdx.x, ct = blockIdx.y, mt = blockIdx.z;
    __shared__ __align__(16) __nv_bfloat16 sAhi[64][40];
    __shared__ __align__(16) __nv_bfloat16 sAlo[64][40];
    __shared__ __align__(16) u32 sB[192][36];
    const int tid = threadIdx.x, lane = tid & 31, warp = tid >> 5;
    const int wm = warp >> 1, wn = warp & 1;
    float d[3][4][4];
    #pragma unroll
    for (int i = 0; i < 3; i++) for (int j = 0; j < 4; j++) for (int k = 0; k < 4; k++) d[i][j][k] = 0.f;
    const int rA = tid >> 2, kc = (tid & 3) * 8;
    uint4 pAh, pAl, pBh[3], pBl[3];
    const __nv_bfloat16* __restrict__ Hhi = g_hhi[rb];
    const __nv_bfloat16* __restrict__ Hlo = g_hlo[rb];
    {
        size_t ao = (size_t)(g * B_ + mt * 64 + rA) * HID + kc;
        pAh = *(const uint4*)(Hhi + ao); pAl = *(const uint4*)(Hlo + ao);
        #pragma unroll
        for (int i = 0; i < 3; i++) {
            int rB = rA + i * 64;
            int j = ((rB >> 6) * HID) + ct * 64 + (rB & 63);
            size_t bo = (size_t)(g * H3 + j) * HID + kc;
            pBh[i] = *(const uint4*)(g_whh_hi + bo); pBl[i] = *(const uint4*)(g_whh_lo + bo);
        }
        *(uint4*)&sAhi[rA][kc] = pAh; *(uint4*)&sAlo[rA][kc] = pAl;
        #pragma unroll
        for (int i = 0; i < 3; i++) {
            int rB = rA + i * 64;
            uint4 h = pBh[i], l = pBl[i], w0, w1;
            w0.x = h.x; w0.y = l.x; w0.z = h.y; w0.w = l.y;
            w1.x = h.z; w1.y = l.z; w1.z = h.w; w1.w = l.w;
            *(uint4*)&sB[rB][kc] = w0; *(uint4*)&sB[rB][kc + 4] = w1;
        }
    }
    __syncthreads();
    const int NIT = HID / 32;
    for (int it = 0; it < NIT; ++it) {
        if (it + 1 < NIT) {
            const int kk = (it + 1) * 32;
            size_t ao = (size_t)(g * B_ + mt * 64 + rA) * HID + kk + kc;
            pAh = *(const uint4*)(Hhi + ao); pAl = *(const uint4*)(Hlo + ao);
            #pragma unroll
            for (int i = 0; i < 3; i++) {
                int rB = rA + i * 64;
                int j = ((rB >> 6) * HID) + ct * 64 + (rB & 63);
                size_t bo = (size_t)(g * H3 + j) * HID + kk + kc;
                pBh[i] = *(const uint4*)(g_whh_hi + bo); pBl[i] = *(const uint4*)(g_whh_lo + bo);
            }
        }
        #pragma unroll
        for (int ks = 0; ks < 2; ks++) {
            u32 ah[4], al[4];
            {
                const int row = wm * 16 + (lane & 15);
                const int col = ks * 16 + ((lane >> 4) << 3);
                ldsm4(ah, &sAhi[row][col]); ldsm4(al, &sAlo[row][col]);
            }
            #pragma unroll
            for (int gi = 0; gi < 3; gi++)
                #pragma unroll
                for (int nf = 0; nf < 4; nf++) {
                    const int n = gi * 64 + wn * 32 + nf * 8 + (lane >> 2);
                    const int w0 = ks * 16 + ((lane & 3) << 1);
                    uint2 q0 = *(const uint2*)&sB[n][w0];
                    uint2 q1 = *(const uint2*)&sB[n][w0 + 8];
                    mma16816(d[gi][nf], ah, q0.x, q1.x);
                    mma16816(d[gi][nf], al, q0.x, q1.x);
                    mma16816(d[gi][nf], ah, q0.y, q1.y);
                }
        }
        if (it + 1 < NIT) {
            __syncthreads();
            *(uint4*)&sAhi[rA][kc] = pAh; *(uint4*)&sAlo[rA][kc] = pAl;
            #pragma unroll
            for (int i = 0; i < 3; i++) {
                int rB = rA + i * 64;
                uint4 h = pBh[i], l = pBl[i], w0, w1;
                w0.x = h.x; w0.y = l.x; w0.z = h.y; w0.w = l.y;
                w1.x = h.z; w1.y = l.z; w1.z = h.w; w1.w = l.w;
                *(uint4*)&sB[rB][kc] = w0; *(uint4*)&sB[rB][kc + 4] = w1;
            }
            __syncthreads();
        }
    }
    const float* __restrict__ xpt = g_xp + (size_t)((g * T_ + t) * B_) * H3;
    #pragma unroll
    for (int nf = 0; nf < 4; nf++)
        #pragma unroll
        for (int e = 0; e < 4; e++) {
            int row = wm * 16 + (lane >> 2) + ((e >> 1) << 3);
            int b = mt * 64 + row;
            int c = ct * 64 + wn * 32 + nf * 8 + ((lane & 3) << 1) + (e & 1);
            float hr = d[0][nf][e] + b_hh[g * H3 + c];
            float hz = d[1][nf][e] + b_hh[g * H3 + HID + c];
            float hn = d[2][nf][e] + b_hh[g * H3 + 2 * HID + c];
            const float* xp = xpt + (size_t)b * H3;
            float xr = xp[c], xz = xp[HID + c], xn = xp[2 * HID + c];
            float r = 1.f / (1.f + __expf(-(xr + hr)));
            float u = 1.f / (1.f + __expf(-(xz + hz)));
            float pre = xn + r * hn;
            float e2 = __expf(2.f * pre);
            float n = 1.f - 2.f / (e2 + 1.f);
            int hidx = (g * B_ + b) * HID + c;
            float hv = (1.f - u) * n + u * g_h[rb][hidx];
            out[((size_t)b * T_ + t) * (G_ * HID) + g * HID + c] = hv;
            g_h[wb][hidx] = hv;
            __nv_bfloat16 hi, lo; bsplit(hv, hi, lo);
            g_hhi[wb][hidx] = hi; g_hlo[wb][hidx] = lo;
        }
}

extern "C" void kernel_launch(void* const* d_in, const int* in_sizes, int n_in,
                              void* d_out, int out_size) {
    (void)in_sizes; (void)n_in; (void)out_size;
    const float* z    = (const float*)d_in[0];
    const float* a    = (const float*)d_in[1];
    const float* h    = (const float*)d_in[2];
    const float* W_ih = (const float*)d_in[3];
    const float* W_hh = (const float*)d_in[4];
    const float* b_ih = (const float*)d_in[5];
    const float* b_hh = (const float*)d_in[6];
    float* out = (float*)d_out;

    pack_x_kernel<<<(MTOK * KA + 255) / 256, 256>>>(z, a);
    conv_wih_kernel<<<(G_ * H3 * KA + 255) / 256, 256>>>(W_ih);
    conv_whh_kernel<<<(G_ * H3 * HID + 255) / 256, 256>>>(W_hh);
    init_h_kernel<<<(G_ * B_ * HID + 255) / 256, 256>>>(h);

    gemmA_kernel<<<dim3(96, 64), 256>>>(b_ih);

    for (int t = 0; t < T_; ++t) {
        int rb = t & 1, wb = rb ^ 1;
        gru_step_kernel<<<dim3(G_, 8, 2), 256>>>(b_hh, out, t, rb, wb);
    }
}

// round 9
// speedup vs baseline: 1.5307x; 1.5307x over previous
#include <cuda_runtime.h>
#include <cuda_fp16.h>
#include <cstdint>

typedef unsigned int u32;

#define B_   128
#define T_   64
#define G_   8
#define HID  512
#define H3   1536
#define IN_  1028
#define KA   1056           // 33 * 32
#define MTOK (B_*T_)

// ---------------- device scratch ----------------
__device__ __align__(16) __half g_xhi[MTOK*KA];
__device__ __align__(16) __half g_xlo[MTOK*KA];
__device__ __align__(16) __half g_wih[G_*H3*KA];
__device__ __align__(16) __half g_whh[G_*H3*HID];
__device__ float g_xp[(size_t)G_*T_*B_*H3];
__device__ float g_h[2][G_*B_*HID];
__device__ __align__(16) __half g_hhi[2][G_*B_*HID];
__device__ __align__(16) __half g_hlo[2][G_*B_*HID];

// ---------------- helpers ----------------
__device__ __forceinline__ void hsplit(float v, __half& hi, __half& lo) {
    hi = __float2half_rn(v);
    lo = __float2half_rn(v - __half2float(hi));
}
static __device__ __forceinline__ void cpasync16(u32 s, const void* g) {
    asm volatile("cp.async.cg.shared.global [%0], [%1], 16;" :: "r"(s), "l"(g));
}
static __device__ __forceinline__ void cp_commit() { asm volatile("cp.async.commit_group;" ::: "memory"); }
template<int N> static __device__ __forceinline__ void cp_wait() { asm volatile("cp.async.wait_group %0;" :: "n"(N) : "memory"); }
static __device__ __forceinline__ void ldsm4(u32* r, u32 a) {
    asm volatile("ldmatrix.sync.aligned.m8n8.x4.shared.b16 {%0,%1,%2,%3}, [%4];"
                 : "=r"(r[0]), "=r"(r[1]), "=r"(r[2]), "=r"(r[3]) : "r"(a));
}
static __device__ __forceinline__ void mma_h(float* d, const u32* a, u32 b0, u32 b1) {
    asm volatile("mma.sync.aligned.m16n8k16.row.col.f32.f16.f16.f32 "
                 "{%0,%1,%2,%3}, {%4,%5,%6,%7}, {%8,%9}, {%0,%1,%2,%3};"
                 : "+f"(d[0]), "+f"(d[1]), "+f"(d[2]), "+f"(d[3])
                 : "r"(a[0]), "r"(a[1]), "r"(a[2]), "r"(a[3]), "r"(b0), "r"(b1));
}

// ---------------- prep kernels ----------------
__global__ void pack_x_kernel(const float* __restrict__ z, const float* __restrict__ a) {
    int idx = blockIdx.x * blockDim.x + threadIdx.x;
    if (idx >= MTOK * KA) return;
    int m = idx / KA, k = idx - m * KA;
    int b = m >> 6, t = m & 63;
    float v = 0.f;
    if (k < 4)        v = a[(size_t)(b * T_ + t) * 4 + k];
    else if (k < IN_) v = z[(size_t)(b * T_ + t) * 1024 + (k - 4)];
    __half hi, lo; hsplit(v, hi, lo);
    g_xhi[idx] = hi; g_xlo[idx] = lo;
}
__global__ void conv_wih_kernel(const float* __restrict__ W) {
    int idx = blockIdx.x * blockDim.x + threadIdx.x;
    if (idx >= G_ * H3 * KA) return;
    int row = idx / KA, k = idx - row * KA;
    float v = (k < IN_) ? W[(size_t)row * IN_ + k] : 0.f;
    g_wih[idx] = __float2half_rn(v);
}
__global__ void conv_whh_kernel(const float* __restrict__ W) {
    int idx = blockIdx.x * blockDim.x + threadIdx.x;
    if (idx >= G_ * H3 * HID) return;
    g_whh[idx] = __float2half_rn(W[idx]);
}
__global__ void init_h_kernel(const float* __restrict__ hin) {
    int idx = blockIdx.x * blockDim.x + threadIdx.x;
    if (idx >= G_ * B_ * HID) return;
    int g = idx / (B_ * HID), r = idx - g * B_ * HID;
    int b = r / HID, c = r - b * HID;
    float v = hin[(size_t)b * (G_ * HID) + g * HID + c];
    g_h[0][idx] = v;
    __half hi, lo; hsplit(v, hi, lo);
    g_hhi[0][idx] = hi; g_hlo[0][idx] = lo;
}

// ================= gemmA: xp[m, g*1536+j] = x @ W_ih[g]^T + b_ih =================
// grid (96, 64) = (ntile 128-wide, mtile 128). 256 thr (8 warps: 4m x 2n, warp 32m x 64n).
// BK=32, 2-stage cp.async. Stage: Ahi[128][40] | Alo[128][40] | B[128][40] halves.
#define NITA  33
#define ASTGB 30720
__global__ void __launch_bounds__(256, 2) gemmA_k(const float* __restrict__ b_ih) {
    extern __shared__ char smem[];
    const u32 sb = (u32)__cvta_generic_to_shared(smem);
    const int tid = threadIdx.x, lane = tid & 31, warp = tid >> 5;
    const int nt = blockIdx.x, mt = blockIdx.y;
    const int g = nt / 12, jb = (nt % 12) * 128, m0 = mt * 128;
    const int wm = warp >> 1, wn = warp & 1;

    float d[2][8][4];
    #pragma unroll
    for (int i = 0; i < 2; i++)
        #pragma unroll
        for (int j = 0; j < 8; j++)
            #pragma unroll
            for (int k = 0; k < 4; k++) d[i][j][k] = 0.f;

    auto loadc = [&](int c, int s) {
        const int k0 = c * 32;
        const u32 st = sb + (u32)s * ASTGB;
        #pragma unroll
        for (int i = tid; i < 512; i += 256) {
            int r = i & 127, w = i >> 7;
            u32 doff = (u32)(r * 40 + w * 8) * 2;
            size_t ga = (size_t)(m0 + r) * KA + k0 + w * 8;
            cpasync16(st + doff,         g_xhi + ga);
            cpasync16(st + 10240 + doff, g_xlo + ga);
            size_t gb = (size_t)(g * H3 + jb + r) * KA + k0 + w * 8;
            cpasync16(st + 20480 + doff, g_wih + gb);
        }
    };
    auto comp = [&](int s) {
        const u32 st = sb + (u32)s * ASTGB;
        #pragma unroll
        for (int ks = 0; ks < 2; ks++) {
            u32 ah[2][4], al[2][4];
            #pragma unroll
            for (int mf = 0; mf < 2; mf++) {
                int row = wm * 32 + mf * 16 + (lane & 15);
                int col = ks * 16 + ((lane >> 4) << 3);
                ldsm4(ah[mf], st + (u32)(row * 40 + col) * 2);
                ldsm4(al[mf], st + 10240 + (u32)(row * 40 + col) * 2);
            }
            #pragma unroll
            for (int np = 0; np < 4; np++) {
                int q = lane >> 3, rr = lane & 7;
                int nrow = wn * 64 + np * 16 + ((q >> 1) << 3) + rr;
                int ncol = ks * 16 + ((q & 1) << 3);
                u32 bb[4];
                ldsm4(bb, st + 20480 + (u32)(nrow * 40 + ncol) * 2);
                #pragma unroll
                for (int mf = 0; mf < 2; mf++) {
                    mma_h(d[mf][2 * np],     ah[mf], bb[0], bb[1]);
                    mma_h(d[mf][2 * np],     al[mf], bb[0], bb[1]);
                    mma_h(d[mf][2 * np + 1], ah[mf], bb[2], bb[3]);
                    mma_h(d[mf][2 * np + 1], al[mf], bb[2], bb[3]);
                }
            }
        }
    };

    loadc(0, 0); cp_commit();
    for (int it = 0; it < NITA; ++it) {
        if (it + 1 < NITA) { loadc(it + 1, (it + 1) & 1); cp_commit(); cp_wait<1>(); }
        else cp_wait<0>();
        __syncthreads();
        comp(it & 1);
        __syncthreads();
    }

    const float* bias = b_ih + g * H3 + jb;
    #pragma unroll
    for (int mf = 0; mf < 2; mf++)
        #pragma unroll
        for (int nf = 0; nf < 8; nf++)
            #pragma unroll
            for (int e = 0; e < 4; e++) {
                int row = wm * 32 + mf * 16 + (lane >> 2) + ((e >> 1) << 3);
                int col = wn * 64 + nf * 8 + ((lane & 3) << 1) + (e & 1);
                int m = m0 + row, bb2 = m >> 6, tt = m & 63;
                g_xp[(size_t)((g * T_ + tt) * B_ + bb2) * H3 + jb + col] = d[mf][nf][e] + bias[col];
            }
}

// ================= GRU step: one launch per t. grid (8, 8, 2) = (g, 64-col tile, 64-batch). =================
// 256 thr (8 warps: 4m x 2n, warp 16m x 96n). CTA: 64 batch x 192 (3 gates x 64 cols), K=512.
// Stage: Ahi[64][40] | Alo[64][40] | B[192][40] halves = 25600B. C exchange: [64][196] f32.
#define NITS  16
#define SSTGB 25600
#define CPAD  196
__global__ void __launch_bounds__(256, 2) gru_step_k(const float* __restrict__ b_hh,
                                                     float* __restrict__ out,
                                                     int tcur, int rb, int wb) {
    extern __shared__ char smem[];
    const u32 sb = (u32)__cvta_generic_to_shared(smem);
    const int tid = threadIdx.x, lane = tid & 31, warp = tid >> 5;
    const int g = blockIdx.x, ct = blockIdx.y, mt = blockIdx.z;
    const int wm = warp >> 1, wn = warp & 1;
    const __half* __restrict__ Hhi = g_hhi[rb];
    const __half* __restrict__ Hlo = g_hlo[rb];

    float d[12][4];
    #pragma unroll
    for (int i = 0; i < 12; i++)
        #pragma unroll
        for (int k = 0; k < 4; k++) d[i][k] = 0.f;

    auto loadc = [&](int c, int s) {
        const int k0 = c * 32;
        const u32 st = sb + (u32)s * SSTGB;
        {
            int r = tid >> 2, w = tid & 3;           // 256 A-chunks, 1/thread
            u32 doff = (u32)(r * 40 + w * 8) * 2;
            size_t ga = (size_t)(g * B_ + mt * 64 + r) * HID + k0 + w * 8;
            cpasync16(st + doff,        Hhi + ga);
            cpasync16(st + 5120 + doff, Hlo + ga);
        }
        #pragma unroll
        for (int i = tid; i < 768; i += 256) {       // 768 B-chunks, 3/thread
            int r = i >> 2, w = i & 3;
            int j = g * H3 + (r >> 6) * HID + ct * 64 + (r & 63);
            cpasync16(st + 10240 + (u32)(r * 40 + w * 8) * 2,
                      g_whh + (size_t)j * HID + k0 + w * 8);
        }
    };
    auto comp = [&](int s) {
        const u32 st = sb + (u32)s * SSTGB;
        #pragma unroll
        for (int ks = 0; ks < 2; ks++) {
            u32 ah[4], al[4];
            int row = wm * 16 + (lane & 15);
            int col = ks * 16 + ((lane >> 4) << 3);
            ldsm4(ah, st + (u32)(row * 40 + col) * 2);
            ldsm4(al, st + 5120 + (u32)(row * 40 + col) * 2);
            #pragma unroll
            for (int np = 0; np < 6; np++) {
                int q = lane >> 3, rr = lane & 7;
                int nrow = wn * 96 + np * 16 + ((q >> 1) << 3) + rr;
                int ncol = ks * 16 + ((q & 1) << 3);
                u32 bb[4];
                ldsm4(bb, st + 10240 + (u32)(nrow * 40 + ncol) * 2);
                mma_h(d[2 * np],     ah, bb[0], bb[1]);
                mma_h(d[2 * np],     al, bb[0], bb[1]);
                mma_h(d[2 * np + 1], ah, bb[2], bb[3]);
                mma_h(d[2 * np + 1], al, bb[2], bb[3]);
            }
        }
    };

    loadc(0, 0); cp_commit();
    for (int it = 0; it < NITS; ++it) {
        if (it + 1 < NITS) { loadc(it + 1, (it + 1) & 1); cp_commit(); cp_wait<1>(); }
        else cp_wait<0>();
        __syncthreads();
        comp(it & 1);
        __syncthreads();
    }

    // exchange fragments through smem (rows padded to 196 floats)
    float* C = (float*)smem;
    #pragma unroll
    for (int nf = 0; nf < 12; nf++)
        #pragma unroll
        for (int e = 0; e < 4; e++) {
            int row = wm * 16 + (lane >> 2) + ((e >> 1) << 3);
            int col = wn * 96 + nf * 8 + ((lane & 3) << 1) + (e & 1);
            C[row * CPAD + col] = d[nf][e];
        }
    __syncthreads();

    // fused GRU epilogue: thread -> (batch row bl, 16 cols)
    const int bl = tid >> 2, b = mt * 64 + bl;
    const int c0l = (tid & 3) * 16;
    const float* __restrict__ xprow = g_xp + (size_t)((g * T_ + tcur) * B_ + b) * H3;
    const float* __restrict__ bh = b_hh + g * H3;
    float* __restrict__ orow = out + ((size_t)b * T_ + tcur) * (G_ * HID) + g * HID;
    const int hbase = (g * B_ + b) * HID;
    #pragma unroll
    for (int q = 0; q < 4; q++) {
        int cl = c0l + q * 4;
        int c = ct * 64 + cl;
        float4 hr4 = *(float4*)&C[bl * CPAD + cl];
        float4 hz4 = *(float4*)&C[bl * CPAD + 64 + cl];
        float4 hn4 = *(float4*)&C[bl * CPAD + 128 + cl];
        float4 xr4 = *(const float4*)(xprow + c);
        float4 xz4 = *(const float4*)(xprow + HID + c);
        float4 xn4 = *(const float4*)(xprow + 2 * HID + c);
        float4 ho4 = *(const float4*)(&g_h[rb][hbase + c]);
        float hv[4]; __half hh[4], hl[4];
        #pragma unroll
        for (int i = 0; i < 4; i++) {
            float hr = (&hr4.x)[i] + bh[c + i];
            float hz = (&hz4.x)[i] + bh[HID + c + i];
            float hn = (&hn4.x)[i] + bh[2 * HID + c + i];
            float r = 1.f / (1.f + __expf(-((&xr4.x)[i] + hr)));
            float u = 1.f / (1.f + __expf(-((&xz4.x)[i] + hz)));
            float pre = (&xn4.x)[i] + r * hn;
            float e2 = __expf(2.f * pre);
            float n = 1.f - 2.f / (e2 + 1.f);
            hv[i] = (1.f - u) * n + u * (&ho4.x)[i];
            hsplit(hv[i], hh[i], hl[i]);
        }
        *(float4*)(orow + c) = make_float4(hv[0], hv[1], hv[2], hv[3]);
        *(float4*)(&g_h[wb][hbase + c]) = make_float4(hv[0], hv[1], hv[2], hv[3]);
        __half2* ph = (__half2*)&g_hhi[wb][hbase + c];
        ph[0] = __halves2half2(hh[0], hh[1]); ph[1] = __halves2half2(hh[2], hh[3]);
        __half2* pl = (__half2*)&g_hlo[wb][hbase + c];
        pl[0] = __halves2half2(hl[0], hl[1]); pl[1] = __halves2half2(hl[2], hl[3]);
    }
}

// ---------------- launch ----------------
extern "C" void kernel_launch(void* const* d_in, const int* in_sizes, int n_in,
                              void* d_out, int out_size) {
    (void)in_sizes; (void)n_in; (void)out_size;
    const float* z    = (const float*)d_in[0];
    const float* a    = (const float*)d_in[1];
    const float* h    = (const float*)d_in[2];
    const float* W_ih = (const float*)d_in[3];
    const float* W_hh = (const float*)d_in[4];
    const float* b_ih = (const float*)d_in[5];
    const float* b_hh = (const float*)d_in[6];
    float* out = (float*)d_out;

    cudaFuncSetAttribute(gemmA_k,    cudaFuncAttributeMaxDynamicSharedMemorySize, 2 * ASTGB);
    cudaFuncSetAttribute(gru_step_k, cudaFuncAttributeMaxDynamicSharedMemorySize, 2 * SSTGB);

    pack_x_kernel<<<(MTOK * KA + 255) / 256, 256>>>(z, a);
    conv_wih_kernel<<<(G_ * H3 * KA + 255) / 256, 256>>>(W_ih);
    conv_whh_kernel<<<(G_ * H3 * HID + 255) / 256, 256>>>(W_hh);
    init_h_kernel<<<(G_ * B_ * HID + 255) / 256, 256>>>(h);

    gemmA_k<<<dim3(96, 64), 256, 2 * ASTGB>>>(b_ih);

    for (int t = 0; t < T_; ++t) {
        int rb = t & 1, wb = rb ^ 1;
        gru_step_k<<<dim3(G_, 8, 2), 256, 2 * SSTGB>>>(b_hh, out, t, rb, wb);
    }
}

// round 13
// speedup vs baseline: 2.0604x; 1.3461x over previous
#include <cuda_runtime.h>
#include <cuda_fp16.h>
#include <cstdint>

typedef unsigned int u32;

#define B_   128
#define T_   64
#define G_   8
#define HID  512
#define H3   1536
#define IN_  1028
#define KA   1056           // 33 * 32
#define MTOK (B_*T_)

// ---------------- device scratch ----------------
__device__ __align__(16) __half g_x[MTOK*KA];
__device__ __align__(16) __half g_wih[G_*H3*KA];
__device__ __align__(16) __half g_whh[G_*H3*HID];
__device__ float g_xp[(size_t)G_*T_*B_*H3];
__device__ float g_h[2][G_*B_*HID];
__device__ __align__(16) __half g_hh[2][G_*B_*HID];

// ---------------- helpers ----------------
static __device__ __forceinline__ void cpasync16(u32 s, const void* g) {
    asm volatile("cp.async.cg.shared.global [%0], [%1], 16;" :: "r"(s), "l"(g));
}
static __device__ __forceinline__ void cp_commit() { asm volatile("cp.async.commit_group;" ::: "memory"); }
template<int N> static __device__ __forceinline__ void cp_wait() { asm volatile("cp.async.wait_group %0;" :: "n"(N) : "memory"); }
static __device__ __forceinline__ void ldsm4(u32* r, u32 a) {
    asm volatile("ldmatrix.sync.aligned.m8n8.x4.shared.b16 {%0,%1,%2,%3}, [%4];"
                 : "=r"(r[0]), "=r"(r[1]), "=r"(r[2]), "=r"(r[3]) : "r"(a));
}
static __device__ __forceinline__ void mma_h(float* d, const u32* a, u32 b0, u32 b1) {
    asm volatile("mma.sync.aligned.m16n8k16.row.col.f32.f16.f16.f32 "
                 "{%0,%1,%2,%3}, {%4,%5,%6,%7}, {%8,%9}, {%0,%1,%2,%3};"
                 : "+f"(d[0]), "+f"(d[1]), "+f"(d[2]), "+f"(d[3])
                 : "r"(a[0]), "r"(a[1]), "r"(a[2]), "r"(a[3]), "r"(b0), "r"(b1));
}

// ---------------- prep kernels ----------------
__global__ void pack_x_kernel(const float* __restrict__ z, const float* __restrict__ a) {
    int idx = blockIdx.x * blockDim.x + threadIdx.x;
    if (idx >= MTOK * KA) return;
    int m = idx / KA, k = idx - m * KA;
    int b = m >> 6, t = m & 63;
    float v = 0.f;
    if (k < 4)        v = a[(size_t)(b * T_ + t) * 4 + k];
    else if (k < IN_) v = z[(size_t)(b * T_ + t) * 1024 + (k - 4)];
    g_x[idx] = __float2half_rn(v);
}
__global__ void conv_wih_kernel(const float* __restrict__ W) {
    int idx = blockIdx.x * blockDim.x + threadIdx.x;
    if (idx >= G_ * H3 * KA) return;
    int row = idx / KA, k = idx - row * KA;
    float v = (k < IN_) ? W[(size_t)row * IN_ + k] : 0.f;
    g_wih[idx] = __float2half_rn(v);
}
__global__ void conv_whh_kernel(const float* __restrict__ W) {
    int idx = blockIdx.x * blockDim.x + threadIdx.x;
    if (idx >= G_ * H3 * HID) return;
    g_whh[idx] = __float2half_rn(W[idx]);
}
__global__ void init_h_kernel(const float* __restrict__ hin) {
    int idx = blockIdx.x * blockDim.x + threadIdx.x;
    if (idx >= G_ * B_ * HID) return;
    int g = idx / (B_ * HID), r = idx - g * B_ * HID;
    int b = r / HID, c = r - b * HID;
    float v = hin[(size_t)b * (G_ * HID) + g * HID + c];
    g_h[0][idx] = v;
    g_hh[0][idx] = __float2half_rn(v);
}

// ================= gemmA: xp[m, g*1536+j] = x @ W_ih[g]^T + b_ih =================
// grid (96, 64) = (ntile 128-wide, mtile 128). 256 thr (8 warps: 4m x 2n, warp 32m x 64n).
// BK=32, 2-stage cp.async. Stage: A[128][40] | B[128][40] halves = 20480 B.
#define NITA  33
#define ASTGB 20480
__global__ void __launch_bounds__(256, 2) gemmA_k(const float* __restrict__ b_ih) {
    extern __shared__ char smem[];
    const u32 sb = (u32)__cvta_generic_to_shared(smem);
    const int tid = threadIdx.x, lane = tid & 31, warp = tid >> 5;
    const int nt = blockIdx.x, mt = blockIdx.y;
    const int g = nt / 12, jb = (nt % 12) * 128, m0 = mt * 128;
    const int wm = warp >> 1, wn = warp & 1;

    float d[2][8][4];
    #pragma unroll
    for (int i = 0; i < 2; i++)
        #pragma unroll
        for (int j = 0; j < 8; j++)
            #pragma unroll
            for (int k = 0; k < 4; k++) d[i][j][k] = 0.f;

    auto loadc = [&](int c, int s) {
        const int k0 = c * 32;
        const u32 st = sb + (u32)s * ASTGB;
        #pragma unroll
        for (int i = tid; i < 512; i += 256) {
            int r = i & 127, w = i >> 7;
            u32 doff = (u32)(r * 40 + w * 8) * 2;
            cpasync16(st + doff,         g_x   + (size_t)(m0 + r) * KA + k0 + w * 8);
            cpasync16(st + 10240 + doff, g_wih + (size_t)(g * H3 + jb + r) * KA + k0 + w * 8);
        }
    };
    auto comp = [&](int s) {
        const u32 st = sb + (u32)s * ASTGB;
        #pragma unroll
        for (int ks = 0; ks < 2; ks++) {
            u32 ah[2][4];
            #pragma unroll
            for (int mf = 0; mf < 2; mf++) {
                int row = wm * 32 + mf * 16 + (lane & 15);
                int col = ks * 16 + ((lane >> 4) << 3);
                ldsm4(ah[mf], st + (u32)(row * 40 + col) * 2);
            }
            #pragma unroll
            for (int np = 0; np < 4; np++) {
                int q = lane >> 3, rr = lane & 7;
                int nrow = wn * 64 + np * 16 + ((q >> 1) << 3) + rr;
                int ncol = ks * 16 + ((q & 1) << 3);
                u32 bb[4];
                ldsm4(bb, st + 10240 + (u32)(nrow * 40 + ncol) * 2);
                #pragma unroll
                for (int mf = 0; mf < 2; mf++) {
                    mma_h(d[mf][2 * np],     ah[mf], bb[0], bb[1]);
                    mma_h(d[mf][2 * np + 1], ah[mf], bb[2], bb[3]);
                }
            }
        }
    };

    loadc(0, 0); cp_commit();
    for (int it = 0; it < NITA; ++it) {
        if (it + 1 < NITA) { loadc(it + 1, (it + 1) & 1); cp_commit(); cp_wait<1>(); }
        else cp_wait<0>();
        __syncthreads();
        comp(it & 1);
        __syncthreads();
    }

    const float* bias = b_ih + g * H3 + jb;
    #pragma unroll
    for (int mf = 0; mf < 2; mf++)
        #pragma unroll
        for (int nf = 0; nf < 8; nf++)
            #pragma unroll
            for (int e = 0; e < 4; e++) {
                int row = wm * 32 + mf * 16 + (lane >> 2) + ((e >> 1) << 3);
                int col = wn * 64 + nf * 8 + ((lane & 3) << 1) + (e & 1);
                int m = m0 + row, bb2 = m >> 6, tt = m & 63;
                g_xp[(size_t)((g * T_ + tt) * B_ + bb2) * H3 + jb + col] = d[mf][nf][e] + bias[col];
            }
}

// ================= GRU step: one launch per t. grid (8, 8, 2) = (g, 64-col, 64-batch). =================
// 256 thr (8 warps: 4m x 2n, warp 16m x 96n). CTA: 64 batch x 192 (3 gates x 64 cols), K=512.
// Stage: A[64][40] | B[192][40] halves = 20480 B. C exchange: [64][196] f32 = 50176 B.
#define NITS  16
#define SSTGB 20480
#define CPAD  196
#define SSMEM 50176
__global__ void __launch_bounds__(256, 2) gru_step_k(const float* __restrict__ b_hh,
                                                     float* __restrict__ out,
                                                     int tcur, int rb, int wb) {
    extern __shared__ char smem[];
    const u32 sb = (u32)__cvta_generic_to_shared(smem);
    const int tid = threadIdx.x, lane = tid & 31, warp = tid >> 5;
    const int g = blockIdx.x, ct = blockIdx.y, mt = blockIdx.z;
    const int wm = warp >> 1, wn = warp & 1;
    const __half* __restrict__ Hh = g_hh[rb];

    float d[12][4];
    #pragma unroll
    for (int i = 0; i < 12; i++)
        #pragma unroll
        for (int k = 0; k < 4; k++) d[i][k] = 0.f;

    auto loadc = [&](int c, int s) {
        const int k0 = c * 32;
        const u32 st = sb + (u32)s * SSTGB;
        {
            int r = tid >> 2, w = tid & 3;           // 256 A-chunks, 1/thread
            cpasync16(st + (u32)(r * 40 + w * 8) * 2,
                      Hh + (size_t)(g * B_ + mt * 64 + r) * HID + k0 + w * 8);
        }
        #pragma unroll
        for (int i = tid; i < 768; i += 256) {       // 768 B-chunks, 3/thread
            int r = i >> 2, w = i & 3;
            int j = g * H3 + (r >> 6) * HID + ct * 64 + (r & 63);
            cpasync16(st + 5120 + (u32)(r * 40 + w * 8) * 2,
                      g_whh + (size_t)j * HID + k0 + w * 8);
        }
    };
    auto comp = [&](int s) {
        const u32 st = sb + (u32)s * SSTGB;
        #pragma unroll
        for (int ks = 0; ks < 2; ks++) {
            u32 ah[4];
            int row = wm * 16 + (lane & 15);
            int col = ks * 16 + ((lane >> 4) << 3);
            ldsm4(ah, st + (u32)(row * 40 + col) * 2);
            #pragma unroll
            for (int np = 0; np < 6; np++) {
                int q = lane >> 3, rr = lane & 7;
                int nrow = wn * 96 + np * 16 + ((q >> 1) << 3) + rr;
                int ncol = ks * 16 + ((q & 1) << 3);
                u32 bb[4];
                ldsm4(bb, st + 5120 + (u32)(nrow * 40 + ncol) * 2);
                mma_h(d[2 * np],     ah, bb[0], bb[1]);
                mma_h(d[2 * np + 1], ah, bb[2], bb[3]);
            }
        }
    };

    loadc(0, 0); cp_commit();
    for (int it = 0; it < NITS; ++it) {
        if (it + 1 < NITS) { loadc(it + 1, (it + 1) & 1); cp_commit(); cp_wait<1>(); }
        else cp_wait<0>();
        __syncthreads();
        comp(it & 1);
        __syncthreads();
    }

    // exchange fragments through smem (rows padded to 196 floats)
    float* C = (float*)smem;
    #pragma unroll
    for (int nf = 0; nf < 12; nf++)
        #pragma unroll
        for (int e = 0; e < 4; e++) {
            int row = wm * 16 + (lane >> 2) + ((e >> 1) << 3);
            int col = wn * 96 + nf * 8 + ((lane & 3) << 1) + (e & 1);
            C[row * CPAD + col] = d[nf][e];
        }
    __syncthreads();

    // fused GRU epilogue: thread -> (batch row bl, 16 cols)
    const int bl = tid >> 2, b = mt * 64 + bl;
    const int c0l = (tid & 3) * 16;
    const float* __restrict__ xprow = g_xp + (size_t)((g * T_ + tcur) * B_ + b) * H3;
    const float* __restrict__ bh = b_hh + g * H3;
    float* __restrict__ orow = out + ((size_t)b * T_ + tcur) * (G_ * HID) + g * HID;
    const int hbase = (g * B_ + b) * HID;
    #pragma unroll
    for (int q = 0; q < 4; q++) {
        int cl = c0l + q * 4;
        int c = ct * 64 + cl;
        float4 hr4 = *(float4*)&C[bl * CPAD + cl];
        float4 hz4 = *(float4*)&C[bl * CPAD + 64 + cl];
        float4 hn4 = *(float4*)&C[bl * CPAD + 128 + cl];
        float4 xr4 = *(const float4*)(xprow + c);
        float4 xz4 = *(const float4*)(xprow + HID + c);
        float4 xn4 = *(const float4*)(xprow + 2 * HID + c);
        float4 ho4 = *(const float4*)(&g_h[rb][hbase + c]);
        float hv[4]; __half hq[4];
        #pragma unroll
        for (int i = 0; i < 4; i++) {
            float hr = (&hr4.x)[i] + bh[c + i];
            float hz = (&hz4.x)[i] + bh[HID + c + i];
            float hn = (&hn4.x)[i] + bh[2 * HID + c + i];
            float r = 1.f / (1.f + __expf(-((&xr4.x)[i] + hr)));
            float u = 1.f / (1.f + __expf(-((&xz4.x)[i] + hz)));
            float pre = (&xn4.x)[i] + r * hn;
            float e2 = __expf(2.f * pre);
            float n = 1.f - 2.f / (e2 + 1.f);
            hv[i] = (1.f - u) * n + u * (&ho4.x)[i];
            hq[i] = __float2half_rn(hv[i]);
        }
        *(float4*)(orow + c) = make_float4(hv[0], hv[1], hv[2], hv[3]);
        *(float4*)(&g_h[wb][hbase + c]) = make_float4(hv[0], hv[1], hv[2], hv[3]);
        __half2* ph = (__half2*)&g_hh[wb][hbase + c];
        ph[0] = __halves2half2(hq[0], hq[1]); ph[1] = __halves2half2(hq[2], hq[3]);
    }
}

// ---------------- launch ----------------
extern "C" void kernel_launch(void* const* d_in, const int* in_sizes, int n_in,
                              void* d_out, int out_size) {
    (void)in_sizes; (void)n_in; (void)out_size;
    const float* z    = (const float*)d_in[0];
    const float* a    = (const float*)d_in[1];
    const float* h    = (const float*)d_in[2];
    const float* W_ih = (const float*)d_in[3];
    const float* W_hh = (const float*)d_in[4];
    const float* b_ih = (const float*)d_in[5];
    const float* b_hh = (const float*)d_in[6];
    float* out = (float*)d_out;

    cudaFuncSetAttribute(gemmA_k,    cudaFuncAttributeMaxDynamicSharedMemorySize, 2 * ASTGB);
    cudaFuncSetAttribute(gru_step_k, cudaFuncAttributeMaxDynamicSharedMemorySize, SSMEM);

    pack_x_kernel<<<(MTOK * KA + 255) / 256, 256>>>(z, a);
    conv_wih_kernel<<<(G_ * H3 * KA + 255) / 256, 256>>>(W_ih);
    conv_whh_kernel<<<(G_ * H3 * HID + 255) / 256, 256>>>(W_hh);
    init_h_kernel<<<(G_ * B_ * HID + 255) / 256, 256>>>(h);

    gemmA_k<<<dim3(96, 64), 256, 2 * ASTGB>>>(b_ih);

    for (int t = 0; t < T_; ++t) {
        int rb = t & 1, wb = rb ^ 1;
        gru_step_k<<<dim3(G_, 8, 2), 256, SSMEM>>>(b_hh, out, t, rb, wb);
    }
}

// round 14
// speedup vs baseline: 2.2060x; 1.0706x over previous
#include <cuda_runtime.h>
#include <cuda_fp16.h>
#include <cstdint>

typedef unsigned int u32;

#define B_   128
#define T_   64
#define G_   8
#define HID  512
#define H3   1536
#define IN_  1028
#define KA   1056           // 33 * 32
#define MTOK (B_*T_)

// ---------------- device scratch ----------------
__device__ __align__(16) __half g_x[MTOK*KA];
__device__ __align__(16) __half g_wih[G_*H3*KA];
__device__ __align__(16) __half g_whh[G_*H3*HID];
__device__ float g_xp[(size_t)G_*T_*B_*H3];
__device__ float g_h0[G_*B_*HID];
__device__ __align__(16) __half g_hh[2][G_*B_*HID];
__device__ int g_cnt[T_][G_][2];

// ---------------- helpers ----------------
static __device__ __forceinline__ void cpasync16(u32 s, const void* g) {
    asm volatile("cp.async.cg.shared.global [%0], [%1], 16;" :: "r"(s), "l"(g));
}
static __device__ __forceinline__ void cp_commit() { asm volatile("cp.async.commit_group;" ::: "memory"); }
template<int N> static __device__ __forceinline__ void cp_wait() { asm volatile("cp.async.wait_group %0;" :: "n"(N) : "memory"); }
static __device__ __forceinline__ void ldsm4(u32* r, u32 a) {
    asm volatile("ldmatrix.sync.aligned.m8n8.x4.shared.b16 {%0,%1,%2,%3}, [%4];"
                 : "=r"(r[0]), "=r"(r[1]), "=r"(r[2]), "=r"(r[3]) : "r"(a));
}
static __device__ __forceinline__ void mma_h(float* d, const u32* a, u32 b0, u32 b1) {
    asm volatile("mma.sync.aligned.m16n8k16.row.col.f32.f16.f16.f32 "
                 "{%0,%1,%2,%3}, {%4,%5,%6,%7}, {%8,%9}, {%0,%1,%2,%3};"
                 : "+f"(d[0]), "+f"(d[1]), "+f"(d[2]), "+f"(d[3])
                 : "r"(a[0]), "r"(a[1]), "r"(a[2]), "r"(a[3]), "r"(b0), "r"(b1));
}

// ---------------- prep kernels ----------------
__global__ void pack_x_kernel(const float* __restrict__ z, const float* __restrict__ a) {
    int idx = blockIdx.x * blockDim.x + threadIdx.x;
    if (idx >= MTOK * KA) return;
    int m = idx / KA, k = idx - m * KA;
    int b = m >> 6, t = m & 63;
    float v = 0.f;
    if (k < 4)        v = a[(size_t)(b * T_ + t) * 4 + k];
    else if (k < IN_) v = z[(size_t)(b * T_ + t) * 1024 + (k - 4)];
    g_x[idx] = __float2half_rn(v);
}
__global__ void conv_wih_kernel(const float* __restrict__ W) {
    int idx = blockIdx.x * blockDim.x + threadIdx.x;
    if (idx >= G_ * H3 * KA) return;
    int row = idx / KA, k = idx - row * KA;
    float v = (k < IN_) ? W[(size_t)row * IN_ + k] : 0.f;
    g_wih[idx] = __float2half_rn(v);
}
__global__ void conv_whh_kernel(const float* __restrict__ W) {
    int idx = blockIdx.x * blockDim.x + threadIdx.x;
    if (idx >= G_ * H3 * HID) return;
    g_whh[idx] = __float2half_rn(W[idx]);
}
__global__ void init_h_kernel(const float* __restrict__ hin) {
    int idx = blockIdx.x * blockDim.x + threadIdx.x;
    if (idx < T_ * G_ * 2) ((int*)g_cnt)[idx] = 0;          // reset flags every call
    if (idx >= G_ * B_ * HID) return;
    int g = idx / (B_ * HID), r = idx - g * B_ * HID;
    int b = r / HID, c = r - b * HID;
    float v = hin[(size_t)b * (G_ * HID) + g * HID + c];
    g_h0[idx] = v;
    g_hh[0][idx] = __float2half_rn(v);
}

// ================= gemmA: xp[m, g*1536+j] = x @ W_ih[g]^T + b_ih (unchanged from R13) =============
#define NITA  33
#define ASTGB 20480
__global__ void __launch_bounds__(256, 2) gemmA_k(const float* __restrict__ b_ih) {
    extern __shared__ char smem[];
    const u32 sb = (u32)__cvta_generic_to_shared(smem);
    const int tid = threadIdx.x, lane = tid & 31, warp = tid >> 5;
    const int nt = blockIdx.x, mt = blockIdx.y;
    const int g = nt / 12, jb = (nt % 12) * 128, m0 = mt * 128;
    const int wm = warp >> 1, wn = warp & 1;

    float d[2][8][4];
    #pragma unroll
    for (int i = 0; i < 2; i++)
        #pragma unroll
        for (int j = 0; j < 8; j++)
            #pragma unroll
            for (int k = 0; k < 4; k++) d[i][j][k] = 0.f;

    auto loadc = [&](int c, int s) {
        const int k0 = c * 32;
        const u32 st = sb + (u32)s * ASTGB;
        #pragma unroll
        for (int i = tid; i < 512; i += 256) {
            int r = i & 127, w = i >> 7;
            u32 doff = (u32)(r * 40 + w * 8) * 2;
            cpasync16(st + doff,         g_x   + (size_t)(m0 + r) * KA + k0 + w * 8);
            cpasync16(st + 10240 + doff, g_wih + (size_t)(g * H3 + jb + r) * KA + k0 + w * 8);
        }
    };
    auto comp = [&](int s) {
        const u32 st = sb + (u32)s * ASTGB;
        #pragma unroll
        for (int ks = 0; ks < 2; ks++) {
            u32 ah[2][4];
            #pragma unroll
            for (int mf = 0; mf < 2; mf++) {
                int row = wm * 32 + mf * 16 + (lane & 15);
                int col = ks * 16 + ((lane >> 4) << 3);
                ldsm4(ah[mf], st + (u32)(row * 40 + col) * 2);
            }
            #pragma unroll
            for (int np = 0; np < 4; np++) {
                int q = lane >> 3, rr = lane & 7;
                int nrow = wn * 64 + np * 16 + ((q >> 1) << 3) + rr;
                int ncol = ks * 16 + ((q & 1) << 3);
                u32 bb[4];
                ldsm4(bb, st + 10240 + (u32)(nrow * 40 + ncol) * 2);
                #pragma unroll
                for (int mf = 0; mf < 2; mf++) {
                    mma_h(d[mf][2 * np],     ah[mf], bb[0], bb[1]);
                    mma_h(d[mf][2 * np + 1], ah[mf], bb[2], bb[3]);
                }
            }
        }
    };

    loadc(0, 0); cp_commit();
    for (int it = 0; it < NITA; ++it) {
        if (it + 1 < NITA) { loadc(it + 1, (it + 1) & 1); cp_commit(); cp_wait<1>(); }
        else cp_wait<0>();
        __syncthreads();
        comp(it & 1);
        __syncthreads();
    }

    const float* bias = b_ih + g * H3 + jb;
    #pragma unroll
    for (int mf = 0; mf < 2; mf++)
        #pragma unroll
        for (int nf = 0; nf < 8; nf++)
            #pragma unroll
            for (int e = 0; e < 4; e++) {
                int row = wm * 32 + mf * 16 + (lane >> 2) + ((e >> 1) << 3);
                int col = wn * 64 + nf * 8 + ((lane & 3) << 1) + (e & 1);
                int m = m0 + row, bb2 = m >> 6, tt = m & 63;
                g_xp[(size_t)((g * T_ + tt) * B_ + bb2) * H3 + jb + col] = d[mf][nf][e] + bias[col];
            }
}

// ================= Persistent GRU scan: ONE launch for all 64 steps =================
// grid 128 CTAs (all co-resident): bx = g*16 + mt*8 + ct. 256 thr, 8 warps (4m x 2n).
// CTA: 64 batch x 192 N (gate-interleaved: warp-n block = [r|z|n] x 32 hidden cols), K=512.
// smem: B resident 192x520 halves (199680 B) + A 2-stage 2x5120 = 209920 B.
#define BPADH 520
#define AOFF  199680
#define ASTG2 5120
#define SCAN_SMEM 209920
__global__ void __launch_bounds__(256, 1) gru_scan_k(const float* __restrict__ b_hh,
                                                     float* __restrict__ out) {
    extern __shared__ char smem[];
    const u32 sb = (u32)__cvta_generic_to_shared(smem);
    const int tid = threadIdx.x, lane = tid & 31, warp = tid >> 5;
    const int bx = blockIdx.x;
    const int g = bx >> 4, mt = (bx >> 3) & 1, ct = bx & 7;
    const int wm = warp >> 1, wn = warp & 1;

    // ---- load B (W_hh) once, gate-interleaved, padded rows ----
    for (int i = tid; i < 192 * 64; i += 256) {
        int r = i >> 6, ch = i & 63;
        int wnb = r / 96, rem = r % 96, gate = rem >> 5, cx = rem & 31;
        size_t wrow = (size_t)(g * H3 + gate * HID + ct * 64 + wnb * 32 + cx);
        cpasync16(sb + (u32)r * (BPADH * 2) + ch * 16, g_whh + wrow * HID + ch * 8);
    }
    cp_commit();

    // ---- hoist biases + fp32 h_old into registers ----
    const int rbase = mt * 64 + wm * 16 + (lane >> 2);
    const int cb0 = ct * 64 + wn * 32 + ((lane & 3) << 1);
    float br[8], bz[8], bn[8], hold[2][8];
    #pragma unroll
    for (int q = 0; q < 4; q++)
        #pragma unroll
        for (int p = 0; p < 2; p++) {
            int c = cb0 + 8 * q + p;
            br[2 * q + p] = b_hh[g * H3 + c];
            bz[2 * q + p] = b_hh[g * H3 + HID + c];
            bn[2 * q + p] = b_hh[g * H3 + 2 * HID + c];
        }
    #pragma unroll
    for (int rr = 0; rr < 2; rr++)
        #pragma unroll
        for (int q = 0; q < 4; q++) {
            float2 v = *(const float2*)(g_h0 + (size_t)(g * B_ + rbase + 8 * rr) * HID + cb0 + 8 * q);
            hold[rr][2 * q]     = v.x;
            hold[rr][2 * q + 1] = v.y;
        }

    cp_wait<0>();
    __syncthreads();   // B resident

    for (int t = 0; t < T_; t++) {
        if (t > 0) {
            if (tid == 0) while (atomicAdd(&g_cnt[t - 1][g][mt], 0) < 8) { }
            __syncthreads();
            __threadfence();
        }
        const __half* __restrict__ Hh = g_hh[t & 1];

        float d[12][4];
        #pragma unroll
        for (int i = 0; i < 12; i++)
            #pragma unroll
            for (int k = 0; k < 4; k++) d[i][k] = 0.f;

        auto loadA = [&](int c, int s) {
            int r = tid >> 2, w = tid & 3;
            cpasync16(sb + AOFF + (u32)s * ASTG2 + (u32)(r * 40 + w * 8) * 2,
                      Hh + (size_t)(g * B_ + mt * 64 + r) * HID + c * 32 + w * 8);
        };

        loadA(0, 0); cp_commit();
        for (int it = 0; it < 16; ++it) {
            if (it + 1 < 16) { loadA(it + 1, (it + 1) & 1); cp_commit(); cp_wait<1>(); }
            else cp_wait<0>();
            __syncthreads();
            {
                const u32 ast = sb + AOFF + (u32)(it & 1) * ASTG2;
                #pragma unroll
                for (int ks = 0; ks < 2; ks++) {
                    u32 ah[4];
                    int row = wm * 16 + (lane & 15);
                    int col = ks * 16 + ((lane >> 4) << 3);
                    ldsm4(ah, ast + (u32)(row * 40 + col) * 2);
                    #pragma unroll
                    for (int np = 0; np < 6; np++) {
                        int q = lane >> 3, rr2 = lane & 7;
                        int brow = wn * 96 + np * 16 + ((q >> 1) << 3) + rr2;
                        int bcol = it * 32 + ks * 16 + ((q & 1) << 3);
                        u32 bb[4];
                        ldsm4(bb, sb + (u32)(brow * BPADH + bcol) * 2);
                        mma_h(d[2 * np],     ah, bb[0], bb[1]);
                        mma_h(d[2 * np + 1], ah, bb[2], bb[3]);
                    }
                }
            }
            __syncthreads();
        }

        // ---- fused GRU epilogue: all in registers (gate triples are thread-local) ----
        __half* __restrict__ hwr = g_hh[(t + 1) & 1];
        #pragma unroll
        for (int rr = 0; rr < 2; rr++) {
            const int b = rbase + 8 * rr;
            const float* __restrict__ xp = g_xp + (size_t)((g * T_ + t) * B_ + b) * H3;
            float* __restrict__ orow = out + ((size_t)b * T_ + t) * (G_ * HID) + g * HID;
            __half* __restrict__ hrow = hwr + (size_t)(g * B_ + b) * HID;
            #pragma unroll
            for (int q = 0; q < 4; q++) {
                const int c = cb0 + 8 * q;
                float2 xr = *(const float2*)(xp + c);
                float2 xz = *(const float2*)(xp + HID + c);
                float2 xn = *(const float2*)(xp + 2 * HID + c);
                float2 ov;
                __half hq[2];
                #pragma unroll
                for (int p = 0; p < 2; p++) {
                    int e = rr * 2 + p;
                    float hr = d[q][e]     + br[2 * q + p];
                    float hz = d[4 + q][e] + bz[2 * q + p];
                    float hn = d[8 + q][e] + bn[2 * q + p];
                    float r = 1.f / (1.f + __expf(-((&xr.x)[p] + hr)));
                    float u = 1.f / (1.f + __expf(-((&xz.x)[p] + hz)));
                    float pre = (&xn.x)[p] + r * hn;
                    float e2 = __expf(2.f * pre);
                    float n = 1.f - 2.f / (e2 + 1.f);
                    float hv = (1.f - u) * n + u * hold[rr][2 * q + p];
                    hold[rr][2 * q + p] = hv;
                    (&ov.x)[p] = hv;
                    hq[p] = __float2half_rn(hv);
                }
                *(float2*)(orow + c) = ov;
                *(__half2*)(hrow + c) = __halves2half2(hq[0], hq[1]);
            }
        }

        __threadfence();
        __syncthreads();
        if (tid == 0) atomicAdd(&g_cnt[t][g][mt], 1);
    }
}

// ---------------- launch ----------------
extern "C" void kernel_launch(void* const* d_in, const int* in_sizes, int n_in,
                              void* d_out, int out_size) {
    (void)in_sizes; (void)n_in; (void)out_size;
    const float* z    = (const float*)d_in[0];
    const float* a    = (const float*)d_in[1];
    const float* h    = (const float*)d_in[2];
    const float* W_ih = (const float*)d_in[3];
    const float* W_hh = (const float*)d_in[4];
    const float* b_ih = (const float*)d_in[5];
    const float* b_hh = (const float*)d_in[6];
    float* out = (float*)d_out;

    cudaFuncSetAttribute(gemmA_k,    cudaFuncAttributeMaxDynamicSharedMemorySize, 2 * ASTGB);
    cudaFuncSetAttribute(gru_scan_k, cudaFuncAttributeMaxDynamicSharedMemorySize, SCAN_SMEM);

    pack_x_kernel<<<(MTOK * KA + 255) / 256, 256>>>(z, a);
    conv_wih_kernel<<<(G_ * H3 * KA + 255) / 256, 256>>>(W_ih);
    conv_whh_kernel<<<(G_ * H3 * HID + 255) / 256, 256>>>(W_hh);
    init_h_kernel<<<(G_ * B_ * HID + 255) / 256, 256>>>(h);

    gemmA_k<<<dim3(96, 64), 256, 2 * ASTGB>>>(b_ih);

    gru_scan_k<<<128, 256, SCAN_SMEM>>>(b_hh, out);
}